// round 1
// baseline (speedup 1.0000x reference)
#include <cuda_runtime.h>
#include <cuda_bf16.h>

// Problem constants (fixed by reference)
#define BB 32
#define TT 512
#define DD 256
#define FF 256
#define MM (BB * TT)          // 16384
#define KTOT (3 * DD)         // 768
#define MEL 2304
#define NCHUNK (KTOT / 32)    // 24
#define OUT_GATHER_ELEMS (BB * MEL * DD)   // 18874368

// ---------------- device scratch (no allocs allowed) ----------------
__device__ float g_h1[MM * FF];
__device__ float g_h2[MM * FF];
__device__ float g_w1[KTOT * FF];
__device__ float g_w2[KTOT * FF];
__device__ int   g_cum[BB * TT];

// ---------------- weight pack: wp[kk*256 + f] = w[f, d, k], kk = k*256+d ----
__global__ void pack_w_kernel(const float* __restrict__ w, float* __restrict__ wp) {
    int o = blockIdx.x * 256 + threadIdx.x;   // grid 768 x 256 = 196608
    int kk = o >> 8;
    int f  = o & 255;
    int k  = kk >> 8;       // 0..2
    int d  = kk & 255;
    wp[o] = w[(f * DD + d) * 3 + k];
}

// ---------------- fused conv1d(K=3,pad=1) + bias + LayerNorm + ReLU ---------
// GEMM: C[M=16384, 256] = A_im2col[M, 768] * Wp[768, 256]
// Block: 64 rows x 256 cols, 256 threads, 8x8 microtile. Warp ry owns rows
// [ry*8, ry*8+8) completely -> LayerNorm reduction via warp shuffles.
__global__ __launch_bounds__(256, 2)
void conv_ln_relu_kernel(const float* __restrict__ in, const float* __restrict__ wp,
                         const float* __restrict__ cb, const float* __restrict__ lg,
                         const float* __restrict__ lb, float* __restrict__ out) {
    __shared__ float As[32][68];    // [kchunk][row], stride 68 (16B aligned rows-of-8)
    __shared__ float Bs[32][256];   // [kchunk][f]

    const int tid = threadIdx.x;
    const int cx  = tid & 31;       // col group (8 cols each)
    const int ry  = tid >> 5;       // row group == warp id (8 rows each)
    const int m0  = blockIdx.x * 64;

    float acc[8][8];
#pragma unroll
    for (int i = 0; i < 8; ++i)
#pragma unroll
        for (int j = 0; j < 8; ++j) acc[i][j] = 0.f;

    const int ja = tid & 31;    // A-load: lane -> d offset
    const int ia = tid >> 5;    // A-load: warp -> base row
    const int f4 = tid & 63;    // B-load: float4 col
    const int jb = tid >> 6;    // B-load: base k-row

    for (int ch = 0; ch < NCHUNK; ++ch) {
        const int kk0 = ch * 32;
        const int k   = kk0 >> 8;     // which tap (0..2) — chunks never straddle taps
        const int d0  = kk0 & 255;
        const int dt  = k - 1;
        // load A chunk (im2col), coalesced 128B per warp
#pragma unroll
        for (int ii = 0; ii < 8; ++ii) {
            int i  = ia + ii * 8;
            int m  = m0 + i;
            int t  = m & (TT - 1);
            int tt = t + dt;
            float v = 0.f;
            if (tt >= 0 && tt < TT)
                v = in[((m - t + tt) * DD) + d0 + ja];
            As[ja][i] = v;
        }
        // load B chunk (packed weights), fully coalesced float4
#pragma unroll
        for (int jj = 0; jj < 8; ++jj) {
            int j = jb + jj * 4;
            *(float4*)&Bs[j][f4 * 4] = *(const float4*)&wp[(kk0 + j) * FF + f4 * 4];
        }
        __syncthreads();

#pragma unroll
        for (int kc = 0; kc < 32; ++kc) {
            float4 a0 = *(float4*)&As[kc][ry * 8];
            float4 a1 = *(float4*)&As[kc][ry * 8 + 4];
            float4 b0 = *(float4*)&Bs[kc][cx * 8];
            float4 b1 = *(float4*)&Bs[kc][cx * 8 + 4];
            float a[8] = {a0.x, a0.y, a0.z, a0.w, a1.x, a1.y, a1.z, a1.w};
            float b[8] = {b0.x, b0.y, b0.z, b0.w, b1.x, b1.y, b1.z, b1.w};
#pragma unroll
            for (int i = 0; i < 8; ++i)
#pragma unroll
                for (int j = 0; j < 8; ++j)
                    acc[i][j] = fmaf(a[i], b[j], acc[i][j]);
        }
        __syncthreads();
    }

    // epilogue: +bias, LayerNorm over the 256 cols (warp-wide), *g+b, ReLU
    float cbv[8], gv[8], bv[8];
    {
        float4 c0 = *(const float4*)&cb[cx * 8];
        float4 c1 = *(const float4*)&cb[cx * 8 + 4];
        float4 g0 = *(const float4*)&lg[cx * 8];
        float4 g1 = *(const float4*)&lg[cx * 8 + 4];
        float4 d0 = *(const float4*)&lb[cx * 8];
        float4 d1 = *(const float4*)&lb[cx * 8 + 4];
        cbv[0]=c0.x; cbv[1]=c0.y; cbv[2]=c0.z; cbv[3]=c0.w; cbv[4]=c1.x; cbv[5]=c1.y; cbv[6]=c1.z; cbv[7]=c1.w;
        gv[0]=g0.x;  gv[1]=g0.y;  gv[2]=g0.z;  gv[3]=g0.w;  gv[4]=g1.x;  gv[5]=g1.y;  gv[6]=g1.z;  gv[7]=g1.w;
        bv[0]=d0.x;  bv[1]=d0.y;  bv[2]=d0.z;  bv[3]=d0.w;  bv[4]=d1.x;  bv[5]=d1.y;  bv[6]=d1.z;  bv[7]=d1.w;
    }
#pragma unroll
    for (int i = 0; i < 8; ++i) {
        int m = m0 + ry * 8 + i;
        float s = 0.f, q = 0.f;
#pragma unroll
        for (int j = 0; j < 8; ++j) {
            float v = acc[i][j] + cbv[j];
            acc[i][j] = v;
            s += v; q += v * v;
        }
#pragma unroll
        for (int off = 16; off > 0; off >>= 1) {
            s += __shfl_xor_sync(0xffffffffu, s, off);
            q += __shfl_xor_sync(0xffffffffu, q, off);
        }
        float mu  = s * (1.f / 256.f);
        float var = q * (1.f / 256.f) - mu * mu;
        float rs  = rsqrtf(var + 1e-5f);
        float o[8];
#pragma unroll
        for (int j = 0; j < 8; ++j)
            o[j] = fmaxf(fmaf((acc[i][j] - mu) * rs, gv[j], bv[j]), 0.f);
        float4* dst = (float4*)&out[m * FF + cx * 8];
        dst[0] = make_float4(o[0], o[1], o[2], o[3]);
        dst[1] = make_float4(o[4], o[5], o[6], o[7]);
    }
}

// ---------------- dur_pred = relu(h2 @ lin_w + lin_b) -----------------------
__global__ void linear_relu_kernel(const float* __restrict__ h,
                                   const float* __restrict__ lw,
                                   const float* __restrict__ lbias,
                                   float* __restrict__ dur) {
    int warp = threadIdx.x >> 5;
    int lane = threadIdx.x & 31;
    int m = blockIdx.x * 8 + warp;   // grid 2048
    const float* row = h + (size_t)m * FF;
    float s = 0.f;
#pragma unroll
    for (int j = 0; j < 8; ++j) s = fmaf(row[lane + j * 32], lw[lane + j * 32], s);
#pragma unroll
    for (int off = 16; off > 0; off >>= 1) s += __shfl_xor_sync(0xffffffffu, s, off);
    if (lane == 0) dur[m] = fmaxf(s + lbias[0], 0.f);
}

// ---------------- cumsum(target) per batch ----------------------------------
__global__ void cumsum_kernel(const int* __restrict__ target, int* __restrict__ cum) {
    __shared__ int sm[TT];
    int b = blockIdx.x, t = threadIdx.x;
    sm[t] = target[b * TT + t];
    __syncthreads();
#pragma unroll
    for (int off = 1; off < TT; off <<= 1) {
        int v = (t >= off) ? sm[t - off] : 0;
        __syncthreads();
        sm[t] += v;
        __syncthreads();
    }
    cum[b * TT + t] = sm[t];
}

// ---------------- length-regulator gather -----------------------------------
// out[b, t_out, :] = x[b, clip(searchsorted_right(cum[b], t_out), 0, 511), :] * (t_out < total)
__global__ void gather_kernel(const float* __restrict__ x, const int* __restrict__ cum,
                              float* __restrict__ out) {
    __shared__ int sc[TT];
    int b = blockIdx.y;
    for (int i = threadIdx.x; i < TT; i += 256) sc[i] = cum[b * TT + i];
    __syncthreads();
    int total = sc[TT - 1];
    int t_out = blockIdx.x * 4 + (threadIdx.x >> 6);  // grid.x = 576 -> 2304 rows
    int lane  = threadIdx.x & 63;
    int lo = 0, hi = TT;
    while (lo < hi) {
        int mid = (lo + hi) >> 1;
        if (sc[mid] <= t_out) lo = mid + 1; else hi = mid;
    }
    int idx = min(lo, TT - 1);
    bool valid = t_out < total;
    float4 v = make_float4(0.f, 0.f, 0.f, 0.f);
    if (valid)
        v = ((const float4*)(x + ((size_t)(b * TT + idx)) * DD))[lane];
    ((float4*)(out + ((size_t)(b * MEL + t_out)) * DD))[lane] = v;
}

// ---------------- launch ----------------------------------------------------
extern "C" void kernel_launch(void* const* d_in, const int* in_sizes, int n_in,
                              void* d_out, int out_size) {
    const float* x       = (const float*)d_in[0];
    const int*   target  = (const int*)d_in[1];
    // d_in[2] = mel_max_length (compile-time constant 2304)
    const float* conv1_w = (const float*)d_in[3];
    const float* conv1_b = (const float*)d_in[4];
    const float* ln1_g   = (const float*)d_in[5];
    const float* ln1_b   = (const float*)d_in[6];
    const float* conv2_w = (const float*)d_in[7];
    const float* conv2_b = (const float*)d_in[8];
    const float* ln2_g   = (const float*)d_in[9];
    const float* ln2_b   = (const float*)d_in[10];
    const float* lin_w   = (const float*)d_in[11];
    const float* lin_b   = (const float*)d_in[12];

    float* out_gather = (float*)d_out;
    float* out_dur    = (float*)d_out + OUT_GATHER_ELEMS;

    float *h1, *h2, *w1, *w2; int* cum;
    cudaGetSymbolAddress((void**)&h1,  g_h1);
    cudaGetSymbolAddress((void**)&h2,  g_h2);
    cudaGetSymbolAddress((void**)&w1,  g_w1);
    cudaGetSymbolAddress((void**)&w2,  g_w2);
    cudaGetSymbolAddress((void**)&cum, g_cum);

    pack_w_kernel<<<KTOT, 256>>>(conv1_w, w1);
    pack_w_kernel<<<KTOT, 256>>>(conv2_w, w2);
    cumsum_kernel<<<BB, TT>>>(target, cum);

    conv_ln_relu_kernel<<<MM / 64, 256>>>(x,  w1, conv1_b, ln1_g, ln1_b, h1);
    conv_ln_relu_kernel<<<MM / 64, 256>>>(h1, w2, conv2_b, ln2_g, ln2_b, h2);

    linear_relu_kernel<<<MM / 8, 256>>>(h2, lin_w, lin_b, out_dur);

    gather_kernel<<<dim3(MEL / 4, BB), 256>>>(x, cum, out_gather);
}

// round 4
// speedup vs baseline: 1.4863x; 1.4863x over previous
#include <cuda_runtime.h>
#include <cuda_bf16.h>
#include <cstdint>

#define BB 32
#define TT 512
#define DD 256
#define FF 256
#define MM (BB * TT)          // 16384
#define KTOT 768
#define MEL 2304
#define OUT_GATHER_ELEMS (BB * MEL * DD)   // 18874368

// ---------------- device scratch (no allocs allowed) ----------------
__device__ __nv_bfloat16 g_w1h[FF * KTOT];
__device__ __nv_bfloat16 g_w1l[FF * KTOT];
__device__ __nv_bfloat16 g_w2h[FF * KTOT];
__device__ __nv_bfloat16 g_w2l[FF * KTOT];
__device__ __nv_bfloat16 g_h1h[MM * FF];
__device__ __nv_bfloat16 g_h1l[MM * FF];
__device__ int g_cum[BB * TT];

// ---------------- helpers ----------------
__device__ __forceinline__ uint32_t smem_u32(const void* p) {
    uint32_t a;
    asm("{ .reg .u64 t; cvta.to.shared.u64 t, %1; cvt.u32.u64 %0, t; }" : "=r"(a) : "l"(p));
    return a;
}

__device__ __forceinline__ void ldmatrix_x4(uint32_t& r0, uint32_t& r1, uint32_t& r2,
                                            uint32_t& r3, uint32_t addr) {
    asm volatile("ldmatrix.sync.aligned.m8n8.x4.shared.b16 {%0,%1,%2,%3}, [%4];"
                 : "=r"(r0), "=r"(r1), "=r"(r2), "=r"(r3) : "r"(addr));
}

__device__ __forceinline__ void mma_bf16(float* c, uint32_t a0, uint32_t a1, uint32_t a2,
                                         uint32_t a3, uint32_t b0, uint32_t b1) {
    asm volatile(
        "mma.sync.aligned.m16n8k16.row.col.f32.bf16.bf16.f32 "
        "{%0,%1,%2,%3}, {%4,%5,%6,%7}, {%8,%9}, {%0,%1,%2,%3};"
        : "+f"(c[0]), "+f"(c[1]), "+f"(c[2]), "+f"(c[3])
        : "r"(a0), "r"(a1), "r"(a2), "r"(a3), "r"(b0), "r"(b1));
}

__device__ __forceinline__ void split_bf16(float v, __nv_bfloat16& hi, __nv_bfloat16& lo) {
    hi = __float2bfloat16_rn(v);
    lo = __float2bfloat16_rn(v - __bfloat162float(hi));
}

// ---------------- SMEM layout (dynamic) ----------------
// per buffer: A_hi[64*80] A_lo[64*80] B_hi[256*80] B_lo[256*80] = 51200 B
#define A_HI 0
#define A_LO 5120
#define B_HI 10240
#define B_LO 30720
#define BUF_STRIDE 51200
#define P_CB  102400
#define P_LG  103424
#define P_LB  104448
#define P_LW  105472
#define S_SUM 106496
#define S_SQ  107008
#define S_DOT 107520
#define CONV_SMEM 108032

// ---------------- weight pack + bf16 split: wp[f][tap*256+d] = w[f,d,tap] ---
__global__ void pack_w_kernel(const float* __restrict__ w,
                              __nv_bfloat16* __restrict__ wph,
                              __nv_bfloat16* __restrict__ wpl) {
    int o = blockIdx.x * 256 + threadIdx.x;   // 196608 total
    int f = o / KTOT;
    int rem = o - f * KTOT;
    int tap = rem >> 8;
    int d = rem & 255;
    float v = w[(f * DD + d) * 3 + tap];
    __nv_bfloat16 hi, lo;
    split_bf16(v, hi, lo);
    wph[o] = hi; wpl[o] = lo;
}

// ---------------- mma.sync fused conv+bias+LN+ReLU --------------------------
// C[16384,256] = im2col(A)[16384,768] x W[768,256]
// Block: BM=64 x BN=256, BK=32, 8 warps (4m x 2n), warp tile 16x128.
// bf16 3-term split: ah*bh + ah*bl + al*bh, fp32 accum.
template <bool IN_F32, bool OUT_SPLIT>
__global__ void __launch_bounds__(256, 1)
conv_mma_kernel(const float* __restrict__ inf,
                const __nv_bfloat16* __restrict__ inh,
                const __nv_bfloat16* __restrict__ inl,
                const __nv_bfloat16* __restrict__ wph,
                const __nv_bfloat16* __restrict__ wpl,
                const float* __restrict__ cb, const float* __restrict__ lg,
                const float* __restrict__ lb, const float* __restrict__ lw,
                const float* __restrict__ lbias,
                __nv_bfloat16* __restrict__ outh, __nv_bfloat16* __restrict__ outl,
                float* __restrict__ dur) {
    extern __shared__ char smem[];
    const uint32_t sb = smem_u32(smem);
    const int tid = threadIdx.x;
    const int warp = tid >> 5, lane = tid & 31;
    const int wm = warp & 3, wn = warp >> 2;
    const int m0 = blockIdx.x * 64;

    // cache params
    ((float*)(smem + P_CB))[tid] = cb[tid];
    ((float*)(smem + P_LG))[tid] = lg[tid];
    ((float*)(smem + P_LB))[tid] = lb[tid];
    ((float*)(smem + P_LW))[tid] = lw[tid];

    float acc[16][4];
#pragma unroll
    for (int j = 0; j < 16; ++j)
#pragma unroll
        for (int e = 0; e < 4; ++e) acc[j][e] = 0.f;

    const int lrow = tid >> 2;     // 0..63
    const int lq   = tid & 3;      // 16B unit within 64B row payload

    // fragment smem offsets (within buffer)
    const uint32_t a_off = (uint32_t)((wm * 16 + (lane & 15)) * 80 + ((lane >> 4) & 1) * 16);
    uint32_t b_off[8];
#pragma unroll
    for (int jp = 0; jp < 8; ++jp)
        b_off[jp] = (uint32_t)((wn * 128 + jp * 16 + (lane & 7) + ((lane >> 4) & 1) * 8) * 80 +
                               ((lane >> 3) & 1) * 16);

    // ---- chunk loader ----
    auto load_chunk = [&](int ch) {
        const uint32_t base = (uint32_t)((ch & 1) * BUF_STRIDE);
        const int kk0 = ch * 32;
        const int tap = kk0 >> 8;
        const int d0  = kk0 & 255;
        const int dt  = tap - 1;
        // B tile: 256 rows x 32 bf16 (hi & lo)
#pragma unroll
        for (int p = 0; p < 4; ++p) {
            int f = lrow + p * 64;
            const uint4* sh = (const uint4*)(wph + f * KTOT + kk0);
            const uint4* sl = (const uint4*)(wpl + f * KTOT + kk0);
            *(uint4*)(smem + base + B_HI + f * 80 + lq * 16) = sh[lq];
            *(uint4*)(smem + base + B_LO + f * 80 + lq * 16) = sl[lq];
        }
        // A tile: 64 rows x 32 (im2col with tap shift)
        {
            int r = lrow;
            int m = m0 + r;
            int t = m & (TT - 1);
            int tt = t + dt;
            bool ok = (tt >= 0) && (tt < TT);
            if (IN_F32) {
                float4 v0 = make_float4(0.f, 0.f, 0.f, 0.f), v1 = v0;
                if (ok) {
                    const float4* s = (const float4*)(inf + (size_t)(m + dt) * DD + d0 + lq * 8);
                    v0 = s[0]; v1 = s[1];
                }
                float vv[8] = {v0.x, v0.y, v0.z, v0.w, v1.x, v1.y, v1.z, v1.w};
                __nv_bfloat16 hh[8], ll[8];
#pragma unroll
                for (int e = 0; e < 8; ++e) split_bf16(vv[e], hh[e], ll[e]);
                *(uint4*)(smem + base + A_HI + r * 80 + lq * 16) = *(uint4*)hh;
                *(uint4*)(smem + base + A_LO + r * 80 + lq * 16) = *(uint4*)ll;
            } else {
                uint4 vh = make_uint4(0, 0, 0, 0), vl = vh;
                if (ok) {
                    vh = ((const uint4*)(inh + (size_t)(m + dt) * DD + d0))[lq];
                    vl = ((const uint4*)(inl + (size_t)(m + dt) * DD + d0))[lq];
                }
                *(uint4*)(smem + base + A_HI + r * 80 + lq * 16) = vh;
                *(uint4*)(smem + base + A_LO + r * 80 + lq * 16) = vl;
            }
        }
    };

    load_chunk(0);
    __syncthreads();

    for (int ch = 0; ch < 24; ++ch) {
        if (ch < 23) load_chunk(ch + 1);
        const uint32_t base = sb + (uint32_t)((ch & 1) * BUF_STRIDE);
#pragma unroll
        for (int s = 0; s < 2; ++s) {
            uint32_t ah0, ah1, ah2, ah3, al0, al1, al2, al3;
            ldmatrix_x4(ah0, ah1, ah2, ah3, base + A_HI + a_off + s * 32);
            ldmatrix_x4(al0, al1, al2, al3, base + A_LO + a_off + s * 32);
#pragma unroll
            for (int jp = 0; jp < 8; ++jp) {
                uint32_t bh0, bh1, bh2, bh3, bl0, bl1, bl2, bl3;
                ldmatrix_x4(bh0, bh1, bh2, bh3, base + B_HI + b_off[jp] + s * 32);
                ldmatrix_x4(bl0, bl1, bl2, bl3, base + B_LO + b_off[jp] + s * 32);
                mma_bf16(acc[jp * 2],     ah0, ah1, ah2, ah3, bh0, bh1);
                mma_bf16(acc[jp * 2 + 1], ah0, ah1, ah2, ah3, bh2, bh3);
                mma_bf16(acc[jp * 2],     ah0, ah1, ah2, ah3, bl0, bl1);
                mma_bf16(acc[jp * 2 + 1], ah0, ah1, ah2, ah3, bl2, bl3);
                mma_bf16(acc[jp * 2],     al0, al1, al2, al3, bh0, bh1);
                mma_bf16(acc[jp * 2 + 1], al0, al1, al2, al3, bh2, bh3);
            }
        }
        __syncthreads();
    }

    // ---------------- epilogue: +bias, LayerNorm(256), ReLU -----------------
    const float* scb = (const float*)(smem + P_CB);
    const float* slg = (const float*)(smem + P_LG);
    const float* slb = (const float*)(smem + P_LB);
    const float* slw = (const float*)(smem + P_LW);
    float* ssum = (float*)(smem + S_SUM);   // [2][64]
    float* ssq  = (float*)(smem + S_SQ);
    float* sdot = (float*)(smem + S_DOT);

    float s0 = 0.f, q0 = 0.f, s1 = 0.f, q1 = 0.f;
#pragma unroll
    for (int j = 0; j < 16; ++j) {
        int cj = wn * 128 + j * 8 + (lane & 3) * 2;
        float b0v = scb[cj], b1v = scb[cj + 1];
        acc[j][0] += b0v; acc[j][1] += b1v;
        acc[j][2] += b0v; acc[j][3] += b1v;
        s0 += acc[j][0] + acc[j][1];
        q0 += acc[j][0] * acc[j][0] + acc[j][1] * acc[j][1];
        s1 += acc[j][2] + acc[j][3];
        q1 += acc[j][2] * acc[j][2] + acc[j][3] * acc[j][3];
    }
#pragma unroll
    for (int off = 1; off <= 2; off <<= 1) {
        s0 += __shfl_xor_sync(0xffffffffu, s0, off);
        q0 += __shfl_xor_sync(0xffffffffu, q0, off);
        s1 += __shfl_xor_sync(0xffffffffu, s1, off);
        q1 += __shfl_xor_sync(0xffffffffu, q1, off);
    }
    const int r0 = wm * 16 + (lane >> 2);
    if ((lane & 3) == 0) {
        ssum[wn * 64 + r0] = s0;  ssum[wn * 64 + r0 + 8] = s1;
        ssq[wn * 64 + r0]  = q0;  ssq[wn * 64 + r0 + 8]  = q1;
    }
    __syncthreads();
    float S0 = ssum[r0] + ssum[64 + r0];
    float Q0 = ssq[r0]  + ssq[64 + r0];
    float S1 = ssum[r0 + 8] + ssum[64 + r0 + 8];
    float Q1 = ssq[r0 + 8]  + ssq[64 + r0 + 8];
    float mu0 = S0 * (1.f / 256.f), mu1 = S1 * (1.f / 256.f);
    float rs0 = rsqrtf(Q0 * (1.f / 256.f) - mu0 * mu0 + 1e-5f);
    float rs1 = rsqrtf(Q1 * (1.f / 256.f) - mu1 * mu1 + 1e-5f);

    float dot0 = 0.f, dot1 = 0.f;
#pragma unroll
    for (int j = 0; j < 16; ++j) {
        int cj = wn * 128 + j * 8 + (lane & 3) * 2;
        float g0 = slg[cj], g1 = slg[cj + 1], d0v = slb[cj], d1v = slb[cj + 1];
        float v0 = fmaxf(fmaf((acc[j][0] - mu0) * rs0, g0, d0v), 0.f);
        float v1 = fmaxf(fmaf((acc[j][1] - mu0) * rs0, g1, d1v), 0.f);
        float v2 = fmaxf(fmaf((acc[j][2] - mu1) * rs1, g0, d0v), 0.f);
        float v3 = fmaxf(fmaf((acc[j][3] - mu1) * rs1, g1, d1v), 0.f);
        if (OUT_SPLIT) {
            __nv_bfloat16 h0, l0, h1, l1;
            size_t i0 = (size_t)(m0 + r0) * FF + cj;
            size_t i1 = (size_t)(m0 + r0 + 8) * FF + cj;
            split_bf16(v0, h0, l0); split_bf16(v1, h1, l1);
            *(__nv_bfloat162*)(outh + i0) = __nv_bfloat162(h0, h1);
            *(__nv_bfloat162*)(outl + i0) = __nv_bfloat162(l0, l1);
            split_bf16(v2, h0, l0); split_bf16(v3, h1, l1);
            *(__nv_bfloat162*)(outh + i1) = __nv_bfloat162(h0, h1);
            *(__nv_bfloat162*)(outl + i1) = __nv_bfloat162(l0, l1);
        } else {
            float w0 = slw[cj], w1 = slw[cj + 1];
            dot0 = fmaf(v0, w0, fmaf(v1, w1, dot0));
            dot1 = fmaf(v2, w0, fmaf(v3, w1, dot1));
        }
    }
    if (!OUT_SPLIT) {
#pragma unroll
        for (int off = 1; off <= 2; off <<= 1) {
            dot0 += __shfl_xor_sync(0xffffffffu, dot0, off);
            dot1 += __shfl_xor_sync(0xffffffffu, dot1, off);
        }
        if ((lane & 3) == 0) {
            sdot[wn * 64 + r0] = dot0;
            sdot[wn * 64 + r0 + 8] = dot1;
        }
        __syncthreads();
        if (tid < 64)
            dur[m0 + tid] = fmaxf(sdot[tid] + sdot[64 + tid] + lbias[0], 0.f);
    }
}

// ---------------- cumsum(target) per batch ----------------------------------
__global__ void cumsum_kernel(const int* __restrict__ target, int* __restrict__ cum) {
    __shared__ int sm[TT];
    int b = blockIdx.x, t = threadIdx.x;
    sm[t] = target[b * TT + t];
    __syncthreads();
#pragma unroll
    for (int off = 1; off < TT; off <<= 1) {
        int v = (t >= off) ? sm[t - off] : 0;
        __syncthreads();
        sm[t] += v;
        __syncthreads();
    }
    cum[b * TT + t] = sm[t];
}

// ---------------- length-regulator gather -----------------------------------
__global__ void gather_kernel(const float* __restrict__ x, const int* __restrict__ cum,
                              float* __restrict__ out) {
    __shared__ int sc[TT];
    int b = blockIdx.y;
    for (int i = threadIdx.x; i < TT; i += 256) sc[i] = cum[b * TT + i];
    __syncthreads();
    int total = sc[TT - 1];
    int t_out = blockIdx.x * 4 + (threadIdx.x >> 6);
    int lane  = threadIdx.x & 63;
    int lo = 0, hi = TT;
    while (lo < hi) {
        int mid = (lo + hi) >> 1;
        if (sc[mid] <= t_out) lo = mid + 1; else hi = mid;
    }
    int idx = min(lo, TT - 1);
    bool valid = t_out < total;
    float4 v = make_float4(0.f, 0.f, 0.f, 0.f);
    if (valid)
        v = ((const float4*)(x + ((size_t)(b * TT + idx)) * DD))[lane];
    ((float4*)(out + ((size_t)(b * MEL + t_out)) * DD))[lane] = v;
}

// ---------------- launch ----------------------------------------------------
extern "C" void kernel_launch(void* const* d_in, const int* in_sizes, int n_in,
                              void* d_out, int out_size) {
    const float* x       = (const float*)d_in[0];
    const int*   target  = (const int*)d_in[1];
    const float* conv1_w = (const float*)d_in[3];
    const float* conv1_b = (const float*)d_in[4];
    const float* ln1_g   = (const float*)d_in[5];
    const float* ln1_b   = (const float*)d_in[6];
    const float* conv2_w = (const float*)d_in[7];
    const float* conv2_b = (const float*)d_in[8];
    const float* ln2_g   = (const float*)d_in[9];
    const float* ln2_b   = (const float*)d_in[10];
    const float* lin_w   = (const float*)d_in[11];
    const float* lin_b   = (const float*)d_in[12];

    float* out_gather = (float*)d_out;
    float* out_dur    = (float*)d_out + OUT_GATHER_ELEMS;

    __nv_bfloat16 *w1h, *w1l, *w2h, *w2l, *h1h, *h1l;
    int* cum;
    cudaGetSymbolAddress((void**)&w1h, g_w1h);
    cudaGetSymbolAddress((void**)&w1l, g_w1l);
    cudaGetSymbolAddress((void**)&w2h, g_w2h);
    cudaGetSymbolAddress((void**)&w2l, g_w2l);
    cudaGetSymbolAddress((void**)&h1h, g_h1h);
    cudaGetSymbolAddress((void**)&h1l, g_h1l);
    cudaGetSymbolAddress((void**)&cum, g_cum);

    cudaFuncSetAttribute(conv_mma_kernel<true, true>,
                         cudaFuncAttributeMaxDynamicSharedMemorySize, CONV_SMEM);
    cudaFuncSetAttribute(conv_mma_kernel<false, false>,
                         cudaFuncAttributeMaxDynamicSharedMemorySize, CONV_SMEM);

    pack_w_kernel<<<KTOT, 256>>>(conv1_w, w1h, w1l);
    pack_w_kernel<<<KTOT, 256>>>(conv2_w, w2h, w2l);
    cumsum_kernel<<<BB, TT>>>(target, cum);

    conv_mma_kernel<true, true><<<MM / 64, 256, CONV_SMEM>>>(
        x, nullptr, nullptr, w1h, w1l,
        conv1_b, ln1_g, ln1_b, lin_w, lin_b, h1h, h1l, nullptr);

    conv_mma_kernel<false, false><<<MM / 64, 256, CONV_SMEM>>>(
        nullptr, h1h, h1l, w2h, w2l,
        conv2_b, ln2_g, ln2_b, lin_w, lin_b, nullptr, nullptr, out_dur);

    gather_kernel<<<dim3(MEL / 4, BB), 256>>>(x, cum, out_gather);
}

// round 6
// speedup vs baseline: 1.8300x; 1.2312x over previous
#include <cuda_runtime.h>
#include <cuda_bf16.h>
#include <cstdint>

#define BB 32
#define TT 512
#define DD 256
#define FF 256
#define MM (BB * TT)          // 16384
#define KTOT 768
#define MEL 2304
#define OUT_GATHER_ELEMS (BB * MEL * DD)   // 18874368

// ---------------- device scratch (no allocs allowed) ----------------
__device__ __nv_bfloat16 g_w1h[FF * KTOT];
__device__ __nv_bfloat16 g_w1l[FF * KTOT];
__device__ __nv_bfloat16 g_w2h[FF * KTOT];
__device__ __nv_bfloat16 g_w2l[FF * KTOT];
__device__ __nv_bfloat16 g_xh[MM * DD];
__device__ __nv_bfloat16 g_xl[MM * DD];
__device__ __nv_bfloat16 g_h1h[MM * FF];
__device__ __nv_bfloat16 g_h1l[MM * FF];
__device__ int g_cum[BB * TT];

// ---------------- helpers ----------------
__device__ __forceinline__ uint32_t smem_u32(const void* p) {
    uint32_t a;
    asm("{ .reg .u64 t; cvta.to.shared.u64 t, %1; cvt.u32.u64 %0, t; }" : "=r"(a) : "l"(p));
    return a;
}

__device__ __forceinline__ void ldmatrix_x4(uint32_t& r0, uint32_t& r1, uint32_t& r2,
                                            uint32_t& r3, uint32_t addr) {
    asm volatile("ldmatrix.sync.aligned.m8n8.x4.shared.b16 {%0,%1,%2,%3}, [%4];"
                 : "=r"(r0), "=r"(r1), "=r"(r2), "=r"(r3) : "r"(addr));
}

__device__ __forceinline__ void mma_bf16(float* c, uint32_t a0, uint32_t a1, uint32_t a2,
                                         uint32_t a3, uint32_t b0, uint32_t b1) {
    asm volatile(
        "mma.sync.aligned.m16n8k16.row.col.f32.bf16.bf16.f32 "
        "{%0,%1,%2,%3}, {%4,%5,%6,%7}, {%8,%9}, {%0,%1,%2,%3};"
        : "+f"(c[0]), "+f"(c[1]), "+f"(c[2]), "+f"(c[3])
        : "r"(a0), "r"(a1), "r"(a2), "r"(a3), "r"(b0), "r"(b1));
}

__device__ __forceinline__ void cp16(uint32_t dst, const void* src, uint32_t srcsize) {
    asm volatile("cp.async.cg.shared.global [%0], [%1], 16, %2;"
                 :: "r"(dst), "l"(src), "r"(srcsize) : "memory");
}
#define CP_COMMIT() asm volatile("cp.async.commit_group;" ::: "memory")
#define CP_WAIT1()  asm volatile("cp.async.wait_group 1;" ::: "memory")
#define CP_WAIT0()  asm volatile("cp.async.wait_group 0;" ::: "memory")

__device__ __forceinline__ void split_bf16(float v, __nv_bfloat16& hi, __nv_bfloat16& lo) {
    hi = __float2bfloat16_rn(v);
    lo = __float2bfloat16_rn(v - __bfloat162float(hi));
}

// ---------------- SMEM layout (dynamic), stride-80 rows ----------------
// per stage: A_hi[64*80] A_lo[64*80] B_hi[256*80] B_lo[256*80] = 51200 B
#define A_HI 0
#define A_LO 5120
#define B_HI 10240
#define B_LO 30720
#define STAGE_STRIDE 51200
#define P_CB  102400
#define P_LG  103424
#define P_LB  104448
#define P_LW  105472
#define S_SUM 106496
#define S_SQ  107008
#define S_DOT 107520
#define CONV_SMEM 108032

// ---------------- weight pack + bf16 split ----------------------------------
__global__ void pack_w_kernel(const float* __restrict__ w,
                              __nv_bfloat16* __restrict__ wph,
                              __nv_bfloat16* __restrict__ wpl) {
    int o = blockIdx.x * 256 + threadIdx.x;   // 196608 total
    int f = o / KTOT;
    int rem = o - f * KTOT;
    int tap = rem >> 8;
    int d = rem & 255;
    float v = w[(f * DD + d) * 3 + tap];
    __nv_bfloat16 hi, lo;
    split_bf16(v, hi, lo);
    wph[o] = hi; wpl[o] = lo;
}

// ---------------- x split: f32 -> bf16 hi/lo --------------------------------
__global__ void pack_x_kernel(const float* __restrict__ x,
                              __nv_bfloat16* __restrict__ xh,
                              __nv_bfloat16* __restrict__ xl) {
    int o = (blockIdx.x * 256 + threadIdx.x) * 4;   // 4M elems / 4
    float4 v = *(const float4*)(x + o);
    __nv_bfloat16 h[4], l[4];
    split_bf16(v.x, h[0], l[0]); split_bf16(v.y, h[1], l[1]);
    split_bf16(v.z, h[2], l[2]); split_bf16(v.w, h[3], l[3]);
    *(uint2*)(xh + o) = *(uint2*)h;
    *(uint2*)(xl + o) = *(uint2*)l;
}

// ---------------- cp.async pipelined conv+bias+LN+ReLU ----------------------
// C[16384,256] = im2col(A)[16384,768] x W[768,256]
// Block: BM=64 x BN=256, BK=32, 8 warps (4m x 2n), 2-stage cp.async pipeline,
// 2 CTAs/SM. bf16 3-term split: ah*bh + ah*bl + al*bh, fp32 accum.
template <bool OUT_SPLIT>
__global__ void __launch_bounds__(256, 2)
conv_pipe_kernel(const __nv_bfloat16* __restrict__ inh,
                 const __nv_bfloat16* __restrict__ inl,
                 const __nv_bfloat16* __restrict__ wph,
                 const __nv_bfloat16* __restrict__ wpl,
                 const float* __restrict__ cb, const float* __restrict__ lg,
                 const float* __restrict__ lb, const float* __restrict__ lw,
                 const float* __restrict__ lbias,
                 __nv_bfloat16* __restrict__ outh, __nv_bfloat16* __restrict__ outl,
                 float* __restrict__ dur) {
    extern __shared__ char smem[];
    const uint32_t sb = smem_u32(smem);
    const int tid = threadIdx.x;
    const int warp = tid >> 5, lane = tid & 31;
    const int wm = warp & 3, wn = warp >> 2;
    const int m0 = blockIdx.x * 64;

    ((float*)(smem + P_CB))[tid] = cb[tid];
    ((float*)(smem + P_LG))[tid] = lg[tid];
    ((float*)(smem + P_LB))[tid] = lb[tid];
    ((float*)(smem + P_LW))[tid] = lw[tid];

    float acc[16][4];
#pragma unroll
    for (int j = 0; j < 16; ++j)
#pragma unroll
        for (int e = 0; e < 4; ++e) acc[j][e] = 0.f;

    const int lrow = tid >> 2;     // 0..63
    const int lq   = tid & 3;      // 16B unit within 64B payload

    // A-row source geometry (constant across chunks except tap shift)
    const int am = m0 + lrow;
    const int at = am & (TT - 1);

    // issue one stage's cp.async ops (A 2 + B 8 per thread)
    auto load_stage = [&](int ch) {
        const uint32_t base = sb + (uint32_t)((ch & 1) * STAGE_STRIDE);
        const int kk0 = ch * 32;
        const int tap = kk0 >> 8;
        const int d0  = kk0 & 255;
        const int dt  = tap - 1;
        // A tile
        {
            int tt = at + dt;
            uint32_t ok = (tt >= 0 && tt < TT) ? 16u : 0u;
            int ttc = min(max(tt, 0), TT - 1);
            size_t goff = (size_t)(am - at + ttc) * DD + d0 + lq * 8;
            uint32_t soff = (uint32_t)(lrow * 80 + lq * 16);
            cp16(base + A_HI + soff, inh + goff, ok);
            cp16(base + A_LO + soff, inl + goff, ok);
        }
        // B tile: 256 rows x 32 bf16 (hi & lo)
#pragma unroll
        for (int p = 0; p < 4; ++p) {
            int f = lrow + p * 64;
            size_t goff = (size_t)f * KTOT + kk0 + lq * 8;
            uint32_t soff = (uint32_t)(f * 80 + lq * 16);
            cp16(base + B_HI + soff, wph + goff, 16u);
            cp16(base + B_LO + soff, wpl + goff, 16u);
        }
        CP_COMMIT();
    };

    // fragment smem offsets (within stage)
    const uint32_t a_off = (uint32_t)((wm * 16 + (lane & 15)) * 80 + ((lane >> 4) & 1) * 16);
    uint32_t b_off[8];
#pragma unroll
    for (int jp = 0; jp < 8; ++jp)
        b_off[jp] = (uint32_t)((wn * 128 + jp * 16 + (lane & 7) + ((lane >> 4) & 1) * 8) * 80 +
                               ((lane >> 3) & 1) * 16);

    load_stage(0);
    load_stage(1);

    for (int ch = 0; ch < 24; ++ch) {
        if (ch + 2 < 24) {
            CP_WAIT1();          // stage ch landed (ch+1 may be pending)
        } else {
            CP_WAIT0();
        }
        __syncthreads();         // all cp.async data visible to all warps

        const uint32_t base = sb + (uint32_t)((ch & 1) * STAGE_STRIDE);
#pragma unroll
        for (int s = 0; s < 2; ++s) {
            uint32_t ah0, ah1, ah2, ah3, al0, al1, al2, al3;
            ldmatrix_x4(ah0, ah1, ah2, ah3, base + A_HI + a_off + s * 32);
            ldmatrix_x4(al0, al1, al2, al3, base + A_LO + a_off + s * 32);
#pragma unroll
            for (int jp = 0; jp < 8; ++jp) {
                uint32_t bh0, bh1, bh2, bh3, bl0, bl1, bl2, bl3;
                ldmatrix_x4(bh0, bh1, bh2, bh3, base + B_HI + b_off[jp] + s * 32);
                ldmatrix_x4(bl0, bl1, bl2, bl3, base + B_LO + b_off[jp] + s * 32);
                mma_bf16(acc[jp * 2],     ah0, ah1, ah2, ah3, bh0, bh1);
                mma_bf16(acc[jp * 2 + 1], ah0, ah1, ah2, ah3, bh2, bh3);
                mma_bf16(acc[jp * 2],     ah0, ah1, ah2, ah3, bl0, bl1);
                mma_bf16(acc[jp * 2 + 1], ah0, ah1, ah2, ah3, bl2, bl3);
                mma_bf16(acc[jp * 2],     al0, al1, al2, al3, bh0, bh1);
                mma_bf16(acc[jp * 2 + 1], al0, al1, al2, al3, bh2, bh3);
            }
        }
        __syncthreads();         // done reading this stage; safe to overwrite
        if (ch + 2 < 24) load_stage(ch + 2);
    }

    // ---------------- epilogue: +bias, LayerNorm(256), ReLU -----------------
    const float* scb = (const float*)(smem + P_CB);
    const float* slg = (const float*)(smem + P_LG);
    const float* slb = (const float*)(smem + P_LB);
    const float* slw = (const float*)(smem + P_LW);
    float* ssum = (float*)(smem + S_SUM);   // [2][64]
    float* ssq  = (float*)(smem + S_SQ);
    float* sdot = (float*)(smem + S_DOT);

    float s0 = 0.f, q0 = 0.f, s1 = 0.f, q1 = 0.f;
#pragma unroll
    for (int j = 0; j < 16; ++j) {
        int cj = wn * 128 + j * 8 + (lane & 3) * 2;
        float b0v = scb[cj], b1v = scb[cj + 1];
        acc[j][0] += b0v; acc[j][1] += b1v;
        acc[j][2] += b0v; acc[j][3] += b1v;
        s0 += acc[j][0] + acc[j][1];
        q0 += acc[j][0] * acc[j][0] + acc[j][1] * acc[j][1];
        s1 += acc[j][2] + acc[j][3];
        q1 += acc[j][2] * acc[j][2] + acc[j][3] * acc[j][3];
    }
#pragma unroll
    for (int off = 1; off <= 2; off <<= 1) {
        s0 += __shfl_xor_sync(0xffffffffu, s0, off);
        q0 += __shfl_xor_sync(0xffffffffu, q0, off);
        s1 += __shfl_xor_sync(0xffffffffu, s1, off);
        q1 += __shfl_xor_sync(0xffffffffu, q1, off);
    }
    const int r0 = wm * 16 + (lane >> 2);
    if ((lane & 3) == 0) {
        ssum[wn * 64 + r0] = s0;  ssum[wn * 64 + r0 + 8] = s1;
        ssq[wn * 64 + r0]  = q0;  ssq[wn * 64 + r0 + 8]  = q1;
    }
    __syncthreads();
    float S0 = ssum[r0] + ssum[64 + r0];
    float Q0 = ssq[r0]  + ssq[64 + r0];
    float S1 = ssum[r0 + 8] + ssum[64 + r0 + 8];
    float Q1 = ssq[r0 + 8]  + ssq[64 + r0 + 8];
    float mu0 = S0 * (1.f / 256.f), mu1 = S1 * (1.f / 256.f);
    float rs0 = rsqrtf(Q0 * (1.f / 256.f) - mu0 * mu0 + 1e-5f);
    float rs1 = rsqrtf(Q1 * (1.f / 256.f) - mu1 * mu1 + 1e-5f);

    float dot0 = 0.f, dot1 = 0.f;
#pragma unroll
    for (int j = 0; j < 16; ++j) {
        int cj = wn * 128 + j * 8 + (lane & 3) * 2;
        float g0 = slg[cj], g1 = slg[cj + 1], d0v = slb[cj], d1v = slb[cj + 1];
        float v0 = fmaxf(fmaf((acc[j][0] - mu0) * rs0, g0, d0v), 0.f);
        float v1 = fmaxf(fmaf((acc[j][1] - mu0) * rs0, g1, d1v), 0.f);
        float v2 = fmaxf(fmaf((acc[j][2] - mu1) * rs1, g0, d0v), 0.f);
        float v3 = fmaxf(fmaf((acc[j][3] - mu1) * rs1, g1, d1v), 0.f);
        if (OUT_SPLIT) {
            __nv_bfloat16 h0, l0, h1, l1;
            size_t i0 = (size_t)(m0 + r0) * FF + cj;
            size_t i1 = (size_t)(m0 + r0 + 8) * FF + cj;
            split_bf16(v0, h0, l0); split_bf16(v1, h1, l1);
            *(__nv_bfloat162*)(outh + i0) = __nv_bfloat162(h0, h1);
            *(__nv_bfloat162*)(outl + i0) = __nv_bfloat162(l0, l1);
            split_bf16(v2, h0, l0); split_bf16(v3, h1, l1);
            *(__nv_bfloat162*)(outh + i1) = __nv_bfloat162(h0, h1);
            *(__nv_bfloat162*)(outl + i1) = __nv_bfloat162(l0, l1);
        } else {
            float w0 = slw[cj], w1 = slw[cj + 1];
            dot0 = fmaf(v0, w0, fmaf(v1, w1, dot0));
            dot1 = fmaf(v2, w0, fmaf(v3, w1, dot1));
        }
    }
    if (!OUT_SPLIT) {
#pragma unroll
        for (int off = 1; off <= 2; off <<= 1) {
            dot0 += __shfl_xor_sync(0xffffffffu, dot0, off);
            dot1 += __shfl_xor_sync(0xffffffffu, dot1, off);
        }
        if ((lane & 3) == 0) {
            sdot[wn * 64 + r0] = dot0;
            sdot[wn * 64 + r0 + 8] = dot1;
        }
        __syncthreads();
        if (tid < 64)
            dur[m0 + tid] = fmaxf(sdot[tid] + sdot[64 + tid] + lbias[0], 0.f);
    }
}

// ---------------- cumsum(target) per batch ----------------------------------
__global__ void cumsum_kernel(const int* __restrict__ target, int* __restrict__ cum) {
    __shared__ int sm[TT];
    int b = blockIdx.x, t = threadIdx.x;
    sm[t] = target[b * TT + t];
    __syncthreads();
#pragma unroll
    for (int off = 1; off < TT; off <<= 1) {
        int v = (t >= off) ? sm[t - off] : 0;
        __syncthreads();
        sm[t] += v;
        __syncthreads();
    }
    cum[b * TT + t] = sm[t];
}

// ---------------- length-regulator gather -----------------------------------
__global__ void gather_kernel(const float* __restrict__ x, const int* __restrict__ cum,
                              float* __restrict__ out) {
    __shared__ int sc[TT];
    int b = blockIdx.y;
    for (int i = threadIdx.x; i < TT; i += 256) sc[i] = cum[b * TT + i];
    __syncthreads();
    int total = sc[TT - 1];
    int t_out = blockIdx.x * 4 + (threadIdx.x >> 6);
    int lane  = threadIdx.x & 63;
    int lo = 0, hi = TT;
    while (lo < hi) {
        int mid = (lo + hi) >> 1;
        if (sc[mid] <= t_out) lo = mid + 1; else hi = mid;
    }
    int idx = min(lo, TT - 1);
    bool valid = t_out < total;
    float4 v = make_float4(0.f, 0.f, 0.f, 0.f);
    if (valid)
        v = ((const float4*)(x + ((size_t)(b * TT + idx)) * DD))[lane];
    ((float4*)(out + ((size_t)(b * MEL + t_out)) * DD))[lane] = v;
}

// ---------------- launch ----------------------------------------------------
extern "C" void kernel_launch(void* const* d_in, const int* in_sizes, int n_in,
                              void* d_out, int out_size) {
    const float* x       = (const float*)d_in[0];
    const int*   target  = (const int*)d_in[1];
    const float* conv1_w = (const float*)d_in[3];
    const float* conv1_b = (const float*)d_in[4];
    const float* ln1_g   = (const float*)d_in[5];
    const float* ln1_b   = (const float*)d_in[6];
    const float* conv2_w = (const float*)d_in[7];
    const float* conv2_b = (const float*)d_in[8];
    const float* ln2_g   = (const float*)d_in[9];
    const float* ln2_b   = (const float*)d_in[10];
    const float* lin_w   = (const float*)d_in[11];
    const float* lin_b   = (const float*)d_in[12];

    float* out_gather = (float*)d_out;
    float* out_dur    = (float*)d_out + OUT_GATHER_ELEMS;

    __nv_bfloat16 *w1h, *w1l, *w2h, *w2l, *xh, *xl, *h1h, *h1l;
    int* cum;
    cudaGetSymbolAddress((void**)&w1h, g_w1h);
    cudaGetSymbolAddress((void**)&w1l, g_w1l);
    cudaGetSymbolAddress((void**)&w2h, g_w2h);
    cudaGetSymbolAddress((void**)&w2l, g_w2l);
    cudaGetSymbolAddress((void**)&xh,  g_xh);
    cudaGetSymbolAddress((void**)&xl,  g_xl);
    cudaGetSymbolAddress((void**)&h1h, g_h1h);
    cudaGetSymbolAddress((void**)&h1l, g_h1l);
    cudaGetSymbolAddress((void**)&cum, g_cum);

    cudaFuncSetAttribute(conv_pipe_kernel<true>,
                         cudaFuncAttributeMaxDynamicSharedMemorySize, CONV_SMEM);
    cudaFuncSetAttribute(conv_pipe_kernel<false>,
                         cudaFuncAttributeMaxDynamicSharedMemorySize, CONV_SMEM);

    pack_w_kernel<<<KTOT, 256>>>(conv1_w, w1h, w1l);
    pack_w_kernel<<<KTOT, 256>>>(conv2_w, w2h, w2l);
    pack_x_kernel<<<MM * DD / 1024, 256>>>(x, xh, xl);
    cumsum_kernel<<<BB, TT>>>(target, cum);

    conv_pipe_kernel<true><<<MM / 64, 256, CONV_SMEM>>>(
        xh, xl, w1h, w1l,
        conv1_b, ln1_g, ln1_b, lin_w, lin_b, h1h, h1l, nullptr);

    conv_pipe_kernel<false><<<MM / 64, 256, CONV_SMEM>>>(
        h1h, h1l, w2h, w2l,
        conv2_b, ln2_g, ln2_b, lin_w, lin_b, nullptr, nullptr, out_dur);

    gather_kernel<<<dim3(MEL / 4, BB), 256>>>(x, cum, out_gather);
}

// round 7
// speedup vs baseline: 2.0343x; 1.1116x over previous
#include <cuda_runtime.h>
#include <cuda_bf16.h>
#include <cstdint>

#define BB 32
#define TT 512
#define DD 256
#define FF 256
#define MM (BB * TT)          // 16384
#define KTOT 768
#define MEL 2304
#define OUT_GATHER_ELEMS (BB * MEL * DD)   // 18874368

// ---------------- device scratch (no allocs allowed) ----------------
__device__ __nv_bfloat16 g_w1h[FF * KTOT];
__device__ __nv_bfloat16 g_w1l[FF * KTOT];
__device__ __nv_bfloat16 g_w2h[FF * KTOT];
__device__ __nv_bfloat16 g_w2l[FF * KTOT];
__device__ __nv_bfloat16 g_xh[MM * DD];
__device__ __nv_bfloat16 g_xl[MM * DD];
__device__ __nv_bfloat16 g_h1h[MM * FF];
__device__ __nv_bfloat16 g_h1l[MM * FF];
__device__ int g_cum[BB * TT];

// ---------------- helpers ----------------
__device__ __forceinline__ uint32_t smem_u32(const void* p) {
    uint32_t a;
    asm("{ .reg .u64 t; cvta.to.shared.u64 t, %1; cvt.u32.u64 %0, t; }" : "=r"(a) : "l"(p));
    return a;
}

__device__ __forceinline__ void ldmatrix_x4(uint32_t* r, uint32_t addr) {
    asm volatile("ldmatrix.sync.aligned.m8n8.x4.shared.b16 {%0,%1,%2,%3}, [%4];"
                 : "=r"(r[0]), "=r"(r[1]), "=r"(r[2]), "=r"(r[3]) : "r"(addr));
}

__device__ __forceinline__ void mma_bf16(float* c, const uint32_t* a, uint32_t b0, uint32_t b1) {
    asm volatile(
        "mma.sync.aligned.m16n8k16.row.col.f32.bf16.bf16.f32 "
        "{%0,%1,%2,%3}, {%4,%5,%6,%7}, {%8,%9}, {%0,%1,%2,%3};"
        : "+f"(c[0]), "+f"(c[1]), "+f"(c[2]), "+f"(c[3])
        : "r"(a[0]), "r"(a[1]), "r"(a[2]), "r"(a[3]), "r"(b0), "r"(b1));
}

__device__ __forceinline__ void cp16(uint32_t dst, const void* src, uint32_t srcsize) {
    asm volatile("cp.async.cg.shared.global [%0], [%1], 16, %2;"
                 :: "r"(dst), "l"(src), "r"(srcsize) : "memory");
}
#define CP_COMMIT() asm volatile("cp.async.commit_group;" ::: "memory")
#define CP_WAIT1()  asm volatile("cp.async.wait_group 1;" ::: "memory")
#define CP_WAIT0()  asm volatile("cp.async.wait_group 0;" ::: "memory")

__device__ __forceinline__ void split_bf16(float v, __nv_bfloat16& hi, __nv_bfloat16& lo) {
    hi = __float2bfloat16_rn(v);
    lo = __float2bfloat16_rn(v - __bfloat162float(hi));
}

// ---------------- SMEM layout (dynamic), stride-80 rows ----------------
// per stage: A_hi[128*80] A_lo[128*80] B_hi[256*80] B_lo[256*80] = 61440 B
#define A_HI 0
#define A_LO 10240
#define B_HI 20480
#define B_LO 40960
#define STAGE_STRIDE 61440
#define P_CB  184320
#define P_LG  185344
#define P_LB  186368
#define P_LW  187392
#define S_SUM 188416
#define S_SQ  190464
#define S_DOT 192512
#define CONV_SMEM 194560

// ---------------- merged pack: w1, w2 (split bf16) and x (split bf16) -------
__global__ void pack_all_kernel(const float* __restrict__ w1, const float* __restrict__ w2,
                                const float* __restrict__ x,
                                __nv_bfloat16* __restrict__ w1h, __nv_bfloat16* __restrict__ w1l,
                                __nv_bfloat16* __restrict__ w2h, __nv_bfloat16* __restrict__ w2l,
                                __nv_bfloat16* __restrict__ xh, __nv_bfloat16* __restrict__ xl) {
    int bid = blockIdx.x;
    if (bid < 2 * KTOT) {
        const float* w = (bid < KTOT) ? w1 : w2;
        __nv_bfloat16* wh = (bid < KTOT) ? w1h : w2h;
        __nv_bfloat16* wl = (bid < KTOT) ? w1l : w2l;
        int o = (bid % KTOT) * 256 + threadIdx.x;
        int f = o / KTOT;
        int rem = o - f * KTOT;
        int tap = rem >> 8;
        int d = rem & 255;
        float v = w[(f * DD + d) * 3 + tap];
        __nv_bfloat16 hi, lo;
        split_bf16(v, hi, lo);
        wh[o] = hi; wl[o] = lo;
    } else {
        int o = ((bid - 2 * KTOT) * 256 + threadIdx.x) * 4;
        float4 v = *(const float4*)(x + o);
        __nv_bfloat16 h[4], l[4];
        split_bf16(v.x, h[0], l[0]); split_bf16(v.y, h[1], l[1]);
        split_bf16(v.z, h[2], l[2]); split_bf16(v.w, h[3], l[3]);
        *(uint2*)(xh + o) = *(uint2*)h;
        *(uint2*)(xl + o) = *(uint2*)l;
    }
}

// ---------------- cp.async 3-stage pipelined conv+bias+LN+ReLU --------------
// C[16384,256] = im2col(A)[16384,768] x W[768,256]
// Block: BM=128 x BN=256, BK=32, 512 threads (4m x 4n warps, warp tile 32x64),
// 3-stage cp.async pipeline, ONE __syncthreads per chunk, 1 CTA/SM.
// bf16 3-term split: ah*bh + ah*bl + al*bh, fp32 accum.
template <bool OUT_SPLIT>
__global__ void __launch_bounds__(512, 1)
conv_pipe_kernel(const __nv_bfloat16* __restrict__ inh,
                 const __nv_bfloat16* __restrict__ inl,
                 const __nv_bfloat16* __restrict__ wph,
                 const __nv_bfloat16* __restrict__ wpl,
                 const float* __restrict__ cb, const float* __restrict__ lg,
                 const float* __restrict__ lb, const float* __restrict__ lw,
                 const float* __restrict__ lbias,
                 __nv_bfloat16* __restrict__ outh, __nv_bfloat16* __restrict__ outl,
                 float* __restrict__ dur) {
    extern __shared__ char smem[];
    const uint32_t sb = smem_u32(smem);
    const int tid = threadIdx.x;
    const int warp = tid >> 5, lane = tid & 31;
    const int wm = warp & 3, wn = warp >> 2;      // 4m x 4n
    const int m0 = blockIdx.x * 128;

    if (tid < 256) {
        ((float*)(smem + P_CB))[tid] = cb[tid];
        ((float*)(smem + P_LG))[tid] = lg[tid];
        ((float*)(smem + P_LB))[tid] = lb[tid];
        ((float*)(smem + P_LW))[tid] = lw[tid];
    }

    float acc[2][8][4];
#pragma unroll
    for (int mi = 0; mi < 2; ++mi)
#pragma unroll
        for (int j = 0; j < 8; ++j)
#pragma unroll
            for (int e = 0; e < 4; ++e) acc[mi][j][e] = 0.f;

    const int lrow = tid >> 2;     // 0..127
    const int lq   = tid & 3;      // 16B unit within 64B payload
    const int am = m0 + lrow;
    const int at = am & (TT - 1);

    // one stage's cp.async: A 2 + B 4 per thread
    auto load_stage = [&](int ch) {
        const int bi = ch % 3;
        const uint32_t base = sb + (uint32_t)(bi * STAGE_STRIDE);
        const int kk0 = ch * 32;
        const int tap = kk0 >> 8;
        const int d0  = kk0 & 255;
        const int dt  = tap - 1;
        {
            int tt = at + dt;
            uint32_t ok = (tt >= 0 && tt < TT) ? 16u : 0u;
            int ttc = min(max(tt, 0), TT - 1);
            size_t goff = (size_t)(am - at + ttc) * DD + d0 + lq * 8;
            uint32_t soff = (uint32_t)(lrow * 80 + lq * 16);
            cp16(base + A_HI + soff, inh + goff, ok);
            cp16(base + A_LO + soff, inl + goff, ok);
        }
#pragma unroll
        for (int p = 0; p < 2; ++p) {
            int f = lrow + p * 128;
            size_t goff = (size_t)f * KTOT + kk0 + lq * 8;
            uint32_t soff = (uint32_t)(f * 80 + lq * 16);
            cp16(base + B_HI + soff, wph + goff, 16u);
            cp16(base + B_LO + soff, wpl + goff, 16u);
        }
        CP_COMMIT();
    };

    // fragment smem offsets (within stage)
    uint32_t a_off[2];
#pragma unroll
    for (int mi = 0; mi < 2; ++mi)
        a_off[mi] = (uint32_t)((wm * 32 + mi * 16 + (lane & 15)) * 80 + ((lane >> 4) & 1) * 16);
    uint32_t b_off[4];
#pragma unroll
    for (int jp = 0; jp < 4; ++jp)
        b_off[jp] = (uint32_t)((wn * 64 + jp * 16 + (lane & 7) + ((lane >> 4) & 1) * 8) * 80 +
                               ((lane >> 3) & 1) * 16);

    load_stage(0);
    load_stage(1);

    for (int ch = 0; ch < 24; ++ch) {
        if (ch < 23) { CP_WAIT1(); } else { CP_WAIT0(); }
        __syncthreads();                 // all warps done with chunk ch-1; stage ch visible
        if (ch + 2 < 24) load_stage(ch + 2);   // writes buffer (ch-1)%3 — safe

        const uint32_t base = sb + (uint32_t)((ch % 3) * STAGE_STRIDE);
#pragma unroll
        for (int s = 0; s < 2; ++s) {
            uint32_t ah[2][4], al[2][4];
#pragma unroll
            for (int mi = 0; mi < 2; ++mi) {
                ldmatrix_x4(ah[mi], base + A_HI + a_off[mi] + s * 32);
                ldmatrix_x4(al[mi], base + A_LO + a_off[mi] + s * 32);
            }
#pragma unroll
            for (int jp = 0; jp < 4; ++jp) {
                uint32_t bh[4], bl[4];
                ldmatrix_x4(bh, base + B_HI + b_off[jp] + s * 32);
                ldmatrix_x4(bl, base + B_LO + b_off[jp] + s * 32);
#pragma unroll
                for (int mi = 0; mi < 2; ++mi) {
                    mma_bf16(acc[mi][jp * 2],     ah[mi], bh[0], bh[1]);
                    mma_bf16(acc[mi][jp * 2 + 1], ah[mi], bh[2], bh[3]);
                    mma_bf16(acc[mi][jp * 2],     ah[mi], bl[0], bl[1]);
                    mma_bf16(acc[mi][jp * 2 + 1], ah[mi], bl[2], bl[3]);
                    mma_bf16(acc[mi][jp * 2],     al[mi], bh[0], bh[1]);
                    mma_bf16(acc[mi][jp * 2 + 1], al[mi], bh[2], bh[3]);
                }
            }
        }
    }
    __syncthreads();

    // ---------------- epilogue: +bias, LayerNorm(256), ReLU -----------------
    const float* scb = (const float*)(smem + P_CB);
    const float* slg = (const float*)(smem + P_LG);
    const float* slb = (const float*)(smem + P_LB);
    const float* slw = (const float*)(smem + P_LW);
    float* ssum = (float*)(smem + S_SUM);   // [4][128]
    float* ssq  = (float*)(smem + S_SQ);
    float* sdot = (float*)(smem + S_DOT);

    // add bias, per-thread partial sums for 4 rows (mi x rowhalf)
    float ps[2][2], pq[2][2];
#pragma unroll
    for (int mi = 0; mi < 2; ++mi)
#pragma unroll
        for (int h = 0; h < 2; ++h) { ps[mi][h] = 0.f; pq[mi][h] = 0.f; }

#pragma unroll
    for (int mi = 0; mi < 2; ++mi)
#pragma unroll
        for (int j = 0; j < 8; ++j) {
            int cj = wn * 64 + (j >> 1) * 16 + (j & 1) * 8 + (lane & 3) * 2;
            float b0v = scb[cj], b1v = scb[cj + 1];
            float v0 = acc[mi][j][0] + b0v, v1 = acc[mi][j][1] + b1v;
            float v2 = acc[mi][j][2] + b0v, v3 = acc[mi][j][3] + b1v;
            acc[mi][j][0] = v0; acc[mi][j][1] = v1;
            acc[mi][j][2] = v2; acc[mi][j][3] = v3;
            ps[mi][0] += v0 + v1; pq[mi][0] += v0 * v0 + v1 * v1;
            ps[mi][1] += v2 + v3; pq[mi][1] += v2 * v2 + v3 * v3;
        }
#pragma unroll
    for (int off = 1; off <= 2; off <<= 1)
#pragma unroll
        for (int mi = 0; mi < 2; ++mi)
#pragma unroll
            for (int h = 0; h < 2; ++h) {
                ps[mi][h] += __shfl_xor_sync(0xffffffffu, ps[mi][h], off);
                pq[mi][h] += __shfl_xor_sync(0xffffffffu, pq[mi][h], off);
            }
    const int rbase = wm * 32 + (lane >> 2);
    if ((lane & 3) == 0) {
#pragma unroll
        for (int mi = 0; mi < 2; ++mi)
#pragma unroll
            for (int h = 0; h < 2; ++h) {
                int r = rbase + mi * 16 + h * 8;
                ssum[wn * 128 + r] = ps[mi][h];
                ssq[wn * 128 + r]  = pq[mi][h];
            }
    }
    __syncthreads();

    float dot[2][2] = {{0.f, 0.f}, {0.f, 0.f}};
#pragma unroll
    for (int mi = 0; mi < 2; ++mi)
#pragma unroll
        for (int h = 0; h < 2; ++h) {
            int r = rbase + mi * 16 + h * 8;
            float S = ssum[r] + ssum[128 + r] + ssum[256 + r] + ssum[384 + r];
            float Q = ssq[r]  + ssq[128 + r]  + ssq[256 + r]  + ssq[384 + r];
            float mu = S * (1.f / 256.f);
            float rs = rsqrtf(Q * (1.f / 256.f) - mu * mu + 1e-5f);
#pragma unroll
            for (int j = 0; j < 8; ++j) {
                int cj = wn * 64 + (j >> 1) * 16 + (j & 1) * 8 + (lane & 3) * 2;
                float g0 = slg[cj], g1 = slg[cj + 1];
                float d0v = slb[cj], d1v = slb[cj + 1];
                float v0 = fmaxf(fmaf((acc[mi][j][h * 2]     - mu) * rs, g0, d0v), 0.f);
                float v1 = fmaxf(fmaf((acc[mi][j][h * 2 + 1] - mu) * rs, g1, d1v), 0.f);
                if (OUT_SPLIT) {
                    __nv_bfloat16 h0, l0, h1, l1;
                    split_bf16(v0, h0, l0); split_bf16(v1, h1, l1);
                    size_t idx = (size_t)(m0 + r) * FF + cj;
                    *(__nv_bfloat162*)(outh + idx) = __nv_bfloat162(h0, h1);
                    *(__nv_bfloat162*)(outl + idx) = __nv_bfloat162(l0, l1);
                } else {
                    dot[mi][h] = fmaf(v0, slw[cj], fmaf(v1, slw[cj + 1], dot[mi][h]));
                }
            }
        }
    if (!OUT_SPLIT) {
#pragma unroll
        for (int off = 1; off <= 2; off <<= 1)
#pragma unroll
            for (int mi = 0; mi < 2; ++mi)
#pragma unroll
                for (int h = 0; h < 2; ++h)
                    dot[mi][h] += __shfl_xor_sync(0xffffffffu, dot[mi][h], off);
        if ((lane & 3) == 0) {
#pragma unroll
            for (int mi = 0; mi < 2; ++mi)
#pragma unroll
                for (int h = 0; h < 2; ++h) {
                    int r = rbase + mi * 16 + h * 8;
                    sdot[wn * 128 + r] = dot[mi][h];
                }
        }
        __syncthreads();
        if (tid < 128)
            dur[m0 + tid] = fmaxf(sdot[tid] + sdot[128 + tid] + sdot[256 + tid] +
                                  sdot[384 + tid] + lbias[0], 0.f);
    }
}

// ---------------- cumsum(target) per batch ----------------------------------
__global__ void cumsum_kernel(const int* __restrict__ target, int* __restrict__ cum) {
    __shared__ int sm[TT];
    int b = blockIdx.x, t = threadIdx.x;
    sm[t] = target[b * TT + t];
    __syncthreads();
#pragma unroll
    for (int off = 1; off < TT; off <<= 1) {
        int v = (t >= off) ? sm[t - off] : 0;
        __syncthreads();
        sm[t] += v;
        __syncthreads();
    }
    cum[b * TT + t] = sm[t];
}

// ---------------- length-regulator gather -----------------------------------
__global__ void gather_kernel(const float* __restrict__ x, const int* __restrict__ cum,
                              float* __restrict__ out) {
    __shared__ int sc[TT];
    int b = blockIdx.y;
    for (int i = threadIdx.x; i < TT; i += 256) sc[i] = cum[b * TT + i];
    __syncthreads();
    int total = sc[TT - 1];
    int t_out = blockIdx.x * 4 + (threadIdx.x >> 6);
    int lane  = threadIdx.x & 63;
    int lo = 0, hi = TT;
    while (lo < hi) {
        int mid = (lo + hi) >> 1;
        if (sc[mid] <= t_out) lo = mid + 1; else hi = mid;
    }
    int idx = min(lo, TT - 1);
    bool valid = t_out < total;
    float4 v = make_float4(0.f, 0.f, 0.f, 0.f);
    if (valid)
        v = ((const float4*)(x + ((size_t)(b * TT + idx)) * DD))[lane];
    ((float4*)(out + ((size_t)(b * MEL + t_out)) * DD))[lane] = v;
}

// ---------------- launch ----------------------------------------------------
extern "C" void kernel_launch(void* const* d_in, const int* in_sizes, int n_in,
                              void* d_out, int out_size) {
    const float* x       = (const float*)d_in[0];
    const int*   target  = (const int*)d_in[1];
    const float* conv1_w = (const float*)d_in[3];
    const float* conv1_b = (const float*)d_in[4];
    const float* ln1_g   = (const float*)d_in[5];
    const float* ln1_b   = (const float*)d_in[6];
    const float* conv2_w = (const float*)d_in[7];
    const float* conv2_b = (const float*)d_in[8];
    const float* ln2_g   = (const float*)d_in[9];
    const float* ln2_b   = (const float*)d_in[10];
    const float* lin_w   = (const float*)d_in[11];
    const float* lin_b   = (const float*)d_in[12];

    float* out_gather = (float*)d_out;
    float* out_dur    = (float*)d_out + OUT_GATHER_ELEMS;

    __nv_bfloat16 *w1h, *w1l, *w2h, *w2l, *xh, *xl, *h1h, *h1l;
    int* cum;
    cudaGetSymbolAddress((void**)&w1h, g_w1h);
    cudaGetSymbolAddress((void**)&w1l, g_w1l);
    cudaGetSymbolAddress((void**)&w2h, g_w2h);
    cudaGetSymbolAddress((void**)&w2l, g_w2l);
    cudaGetSymbolAddress((void**)&xh,  g_xh);
    cudaGetSymbolAddress((void**)&xl,  g_xl);
    cudaGetSymbolAddress((void**)&h1h, g_h1h);
    cudaGetSymbolAddress((void**)&h1l, g_h1l);
    cudaGetSymbolAddress((void**)&cum, g_cum);

    cudaFuncSetAttribute(conv_pipe_kernel<true>,
                         cudaFuncAttributeMaxDynamicSharedMemorySize, CONV_SMEM);
    cudaFuncSetAttribute(conv_pipe_kernel<false>,
                         cudaFuncAttributeMaxDynamicSharedMemorySize, CONV_SMEM);

    // packs: w1 (768 blocks) + w2 (768) + x (4096)
    pack_all_kernel<<<2 * KTOT + MM * DD / 1024, 256>>>(
        conv1_w, conv2_w, x, w1h, w1l, w2h, w2l, xh, xl);
    cumsum_kernel<<<BB, TT>>>(target, cum);

    conv_pipe_kernel<true><<<MM / 128, 512, CONV_SMEM>>>(
        xh, xl, w1h, w1l,
        conv1_b, ln1_g, ln1_b, lin_w, lin_b, h1h, h1l, nullptr);

    conv_pipe_kernel<false><<<MM / 128, 512, CONV_SMEM>>>(
        h1h, h1l, w2h, w2l,
        conv2_b, ln2_g, ln2_b, lin_w, lin_b, nullptr, nullptr, out_dur);

    gather_kernel<<<dim3(MEL / 4, BB), 256>>>(x, cum, out_gather);
}